// round 2
// baseline (speedup 1.0000x reference)
#include <cuda_runtime.h>
#include <math.h>
#include <stdint.h>

#define Bsz 32
#define Ssz 2048
#define Isz 256
#define Hsz 256
#define Msz 1024   // 4*H, packed as m = j*4 + g  (g: 0=f,1=i,2=c,3=o)
#define NCTA_REC 128

// ------------------------------- device scratch -------------------------------
__device__ float g_Wx[Isz * Msz];                      // [k][m], x-part rows of W
__device__ float g_Wh[Hsz * Msz];                      // [k][m], h-part rows of W
__device__ float g_bias[Msz];
__device__ float g_xp[(size_t)Bsz * Ssz * Msz];        // [t][b][m]  (256 MB)
__device__ float g_hbuf[2][Bsz * Hsz];                 // double-buffered h, [b][j]
__device__ unsigned g_bar_count;
__device__ unsigned g_bar_gen;

// ------------------------------- pack + reset ---------------------------------
__global__ void pack_kernel(const float* __restrict__ Wf, const float* __restrict__ Wi,
                            const float* __restrict__ Wc, const float* __restrict__ Wo,
                            const float* __restrict__ bf, const float* __restrict__ bi,
                            const float* __restrict__ bc, const float* __restrict__ bo) {
    int idx = blockIdx.x * blockDim.x + threadIdx.x;   // over (k in 0..511, j in 0..255)
    if (idx < 512 * 256) {
        int k = idx >> 8;      // row of W_all (0..511): [0,256) = h-part, [256,512) = x-part
        int j = idx & 255;
        const float* W[4] = {Wf, Wi, Wc, Wo};
        #pragma unroll
        for (int g = 0; g < 4; g++) {
            float v = W[g][k * Hsz + j];
            int m = j * 4 + g;
            if (k < Hsz) g_Wh[k * Msz + m] = v;
            else         g_Wx[(k - Hsz) * Msz + m] = v;
        }
        if (k == 0) {
            const float* bias[4] = {bf, bi, bc, bo};
            #pragma unroll
            for (int g = 0; g < 4; g++) g_bias[j * 4 + g] = bias[g][j];
        }
    }
    if (idx == 0) { g_bar_count = 0; g_bar_gen = 0; }  // barrier reset per launch/replay
}

// ------------------------------- xproj GEMM -----------------------------------
// xp[r][m] = sum_k x_row(r)[k] * Wx[k][m] + bias[m],  r = t*32 + b
#define BM 64
#define BN 64
#define BK 16

__global__ __launch_bounds__(256) void xproj_kernel(const float* __restrict__ x) {
    __shared__ float As[BK][BM + 4];   // +4 pad: conflict-free transposed stores
    __shared__ float Bs[BK][BN];

    int bn = blockIdx.x;               // 0..15   (m blocks)
    int bm = blockIdx.y;               // 0..1023 (row blocks)
    int tid = threadIdx.x;
    int tx = tid & 15, ty = tid >> 4;

    int r0 = bm * BM;
    int m0 = bn * BN;

    int arow = tid >> 2, akq = tid & 3;    // A tile load mapping
    int bk = tid >> 4,  bmq = tid & 15;    // B tile load mapping

    // hoisted global row pointer for A loads
    int r = r0 + arow;
    int b = r & 31, t = r >> 5;
    const float* arow_ptr = x + ((size_t)b * Ssz + t) * Isz;

    float acc[4][4];
    #pragma unroll
    for (int i = 0; i < 4; i++)
        #pragma unroll
        for (int jv = 0; jv < 4; jv++) acc[i][jv] = 0.f;

    for (int k0 = 0; k0 < Isz; k0 += BK) {
        float4 av = *(const float4*)(arow_ptr + k0 + akq * 4);
        As[akq * 4 + 0][arow] = av.x;
        As[akq * 4 + 1][arow] = av.y;
        As[akq * 4 + 2][arow] = av.z;
        As[akq * 4 + 3][arow] = av.w;
        *(float4*)&Bs[bk][bmq * 4] = *(const float4*)(g_Wx + (size_t)(k0 + bk) * Msz + m0 + bmq * 4);
        __syncthreads();
        #pragma unroll
        for (int kk = 0; kk < BK; kk++) {
            float4 a4 = *(float4*)&As[kk][ty * 4];
            float4 b4 = *(float4*)&Bs[kk][tx * 4];
            float ar[4] = {a4.x, a4.y, a4.z, a4.w};
            float br[4] = {b4.x, b4.y, b4.z, b4.w};
            #pragma unroll
            for (int i = 0; i < 4; i++)
                #pragma unroll
                for (int jv = 0; jv < 4; jv++)
                    acc[i][jv] = fmaf(ar[i], br[jv], acc[i][jv]);
        }
        __syncthreads();
    }

    float4 bias4 = *(const float4*)(g_bias + m0 + tx * 4);
    #pragma unroll
    for (int i = 0; i < 4; i++) {
        int rr = r0 + ty * 4 + i;
        float4 o;
        o.x = acc[i][0] + bias4.x;
        o.y = acc[i][1] + bias4.y;
        o.z = acc[i][2] + bias4.z;
        o.w = acc[i][3] + bias4.w;
        *(float4*)(g_xp + (size_t)rr * Msz + m0 + tx * 4) = o;
    }
}

// ------------------------------- persistent recurrence -------------------------
// 128 CTAs x 256 threads. CTA = (jg in 0..31, bq in 0..3). Warp w: j = jg*8 + w,
// b-octet = bq. Lane l covers k in [8l, 8l+8). Wh held in registers (32 f/thread).
// Per step: gemm partials -> 31-shuffle butterfly (lane L ends with value L =
// bb*4+g) -> activations -> c/h update -> grid barrier (double-buffered h).
__global__ __launch_bounds__(256, 1) void lstm_rec(const float* __restrict__ h0,
                                                   const float* __restrict__ c0,
                                                   float* __restrict__ out,
                                                   int write_finals) {
    __shared__ float h_s[8 * Hsz];     // this CTA's 8 batch rows of h

    int cta = blockIdx.x;
    int jg = cta >> 2;
    int bq = cta & 3;
    int tid = threadIdx.x;
    int w = tid >> 5;
    int lane = tid & 31;
    int j = jg * 8 + w;

    // persistent weight registers: wr[kk][g] = Wh[lane*8+kk][4j+g]
    float wr[8][4];
    #pragma unroll
    for (int kk = 0; kk < 8; kk++) {
        float4 v = *(const float4*)(g_Wh + (size_t)(lane * 8 + kk) * Msz + 4 * j);
        wr[kk][0] = v.x; wr[kk][1] = v.y; wr[kk][2] = v.z; wr[kk][3] = v.w;
    }

    int bb_me = lane >> 2;
    int g_me = lane & 3;
    int b_me = bq * 8 + bb_me;
    float c_val = c0[b_me * Hsz + j];   // only meaningful on lanes with g_me==0

    unsigned want = 1;
    const size_t fin_off = (size_t)Bsz * Ssz * Hsz;

    for (int t = 0; t < Ssz; t++) {
        // prefetch this step's x-projection value (used after the reduction)
        float xv = g_xp[((size_t)t * Bsz + b_me) * Msz + 4 * j + g_me];

        // cooperative load of h (prev step) into smem; bypass L1 (stale-line hazard)
        {
            const float4* src4 = (t == 0)
                ? (const float4*)(h0 + bq * 8 * Hsz)
                : (const float4*)(&g_hbuf[(t + 1) & 1][bq * 8 * Hsz]);
            float4* dst4 = (float4*)h_s;
            dst4[tid]       = __ldcg(src4 + tid);
            dst4[tid + 256] = __ldcg(src4 + tid + 256);
        }
        __syncthreads();

        float acc[32];
        #pragma unroll
        for (int v = 0; v < 32; v++) acc[v] = 0.f;

        #pragma unroll
        for (int bb = 0; bb < 8; bb++) {
            float4 hA = *(float4*)&h_s[bb * Hsz + lane * 8];
            float4 hB = *(float4*)&h_s[bb * Hsz + lane * 8 + 4];
            float hv[8] = {hA.x, hA.y, hA.z, hA.w, hB.x, hB.y, hB.z, hB.w};
            #pragma unroll
            for (int kk = 0; kk < 8; kk++)
                #pragma unroll
                for (int g = 0; g < 4; g++)
                    acc[bb * 4 + g] = fmaf(wr[kk][g], hv[kk], acc[bb * 4 + g]);
        }

        // recursive-halving butterfly: reduce 32 values over 32 lanes.
        // After all rounds, lane L holds the full sum of value index L.
        int cnt = 32;
        #pragma unroll
        for (int off = 16; off >= 1; off >>= 1) {
            cnt >>= 1;
            bool upper = (lane & off) != 0;
            #pragma unroll
            for (int v = 0; v < cnt; v++) {
                float send = upper ? acc[v] : acc[v + cnt];
                float recv = __shfl_xor_sync(0xffffffffu, send, off);
                acc[v] = (upper ? acc[v + cnt] : acc[v]) + recv;
            }
        }

        float pre = acc[0] + xv;   // bias already folded into xp
        float a = (g_me == 2) ? tanhf(pre) : (1.f / (1.f + expf(-pre)));

        int base = lane & ~3;
        float fg = __shfl_sync(0xffffffffu, a, base);
        float ig = __shfl_sync(0xffffffffu, a, base + 1);
        float cg = __shfl_sync(0xffffffffu, a, base + 2);
        float og = __shfl_sync(0xffffffffu, a, base + 3);

        if (g_me == 0) {
            c_val = c_val * fg + ig * cg;
            float hn = og * tanhf(c_val);
            g_hbuf[t & 1][b_me * Hsz + j] = hn;
            out[((size_t)b_me * Ssz + t) * Hsz + j] = hn;
            if (write_finals && t == Ssz - 1) {
                out[fin_off + (size_t)b_me * Hsz + j] = hn;                 // h_f
                out[fin_off + (size_t)Bsz * Hsz + (size_t)b_me * Hsz + j] = c_val;  // c_f
            }
        }

        // ---- grid-wide barrier (generation-based, reset each launch by pack) ----
        __syncthreads();   // all h writes + h_s reads of this step done
        if (tid == 0) {
            __threadfence();
            unsigned arr = atomicAdd(&g_bar_count, 1u);
            if (arr == NCTA_REC - 1) {
                atomicExch(&g_bar_count, 0u);
                __threadfence();
                atomicAdd(&g_bar_gen, 1u);
            } else {
                while (*((volatile unsigned*)&g_bar_gen) < want) { }
            }
        }
        __syncthreads();
        want++;
    }
}

// ------------------------------- launch ----------------------------------------
extern "C" void kernel_launch(void* const* d_in, const int* in_sizes, int n_in,
                              void* d_out, int out_size) {
    const float* x  = (const float*)d_in[0];
    const float* h0 = (const float*)d_in[1];
    const float* c0 = (const float*)d_in[2];
    const float* Wf = (const float*)d_in[3];
    const float* bf = (const float*)d_in[4];
    const float* Wi = (const float*)d_in[5];
    const float* bi = (const float*)d_in[6];
    const float* Wc = (const float*)d_in[7];
    const float* bc = (const float*)d_in[8];
    const float* Wo = (const float*)d_in[9];
    const float* bo = (const float*)d_in[10];
    float* out = (float*)d_out;

    int full = Bsz * Ssz * Hsz + 2 * Bsz * Hsz;
    int write_finals = (out_size >= full) ? 1 : 0;

    pack_kernel<<<512, 256>>>(Wf, Wi, Wc, Wo, bf, bi, bc, bo);

    dim3 grid_x(16, 1024);
    xproj_kernel<<<grid_x, 256>>>(x);

    lstm_rec<<<NCTA_REC, 256>>>(h0, c0, out, write_finals);
}

// round 3
// speedup vs baseline: 1.2673x; 1.2673x over previous
#include <cuda_runtime.h>
#include <math.h>
#include <stdint.h>

#define Bsz 32
#define Ssz 2048
#define Isz 256
#define Hsz 256
#define Msz 1024   // 4*H, packed as m = j*4 + g  (g: 0=f,1=i,2=c,3=o)
#define NCTA_REC 128

typedef unsigned long long ull;

// ------------------------------- f32x2 helpers ---------------------------------
__device__ __forceinline__ ull pack2(float lo, float hi) {
    ull r; asm("mov.b64 %0, {%1,%2};" : "=l"(r) : "f"(lo), "f"(hi)); return r;
}
__device__ __forceinline__ void unpack2(float& lo, float& hi, ull v) {
    asm("mov.b64 {%0,%1}, %2;" : "=f"(lo), "=f"(hi) : "l"(v));
}
__device__ __forceinline__ void fma2(ull& d, ull a, ull b) {
    asm("fma.rn.f32x2 %0, %1, %2, %0;" : "+l"(d) : "l"(a), "l"(b));
}
__device__ __forceinline__ ull add2(ull a, ull b) {
    ull r; asm("add.rn.f32x2 %0, %1, %2;" : "=l"(r) : "l"(a), "l"(b)); return r;
}

// ------------------------------- device scratch -------------------------------
__device__ float g_Wx[Isz * Msz];                      // [k][m], x-part rows of W
__device__ float g_Wh[Hsz * Msz];                      // [k][m], h-part rows of W
__device__ float g_bias[Msz];
__device__ float g_xp[(size_t)Bsz * Ssz * Msz];        // [t][b][m]  (256 MB)
__device__ float g_hbuf[2][Bsz * Hsz];                 // double-buffered h, [b][j]
__device__ unsigned g_bar_count;                       // monotonic arrival counter

// ------------------------------- pack + reset ---------------------------------
__global__ void pack_kernel(const float* __restrict__ Wf, const float* __restrict__ Wi,
                            const float* __restrict__ Wc, const float* __restrict__ Wo,
                            const float* __restrict__ bf, const float* __restrict__ bi,
                            const float* __restrict__ bc, const float* __restrict__ bo) {
    int idx = blockIdx.x * blockDim.x + threadIdx.x;   // over (k in 0..511, j in 0..255)
    if (idx < 512 * 256) {
        int k = idx >> 8;      // row of W_all (0..511): [0,256) = h-part, [256,512) = x-part
        int j = idx & 255;
        const float* W[4] = {Wf, Wi, Wc, Wo};
        #pragma unroll
        for (int g = 0; g < 4; g++) {
            float v = W[g][k * Hsz + j];
            int m = j * 4 + g;
            if (k < Hsz) g_Wh[k * Msz + m] = v;
            else         g_Wx[(k - Hsz) * Msz + m] = v;
        }
        if (k == 0) {
            const float* bias[4] = {bf, bi, bc, bo};
            #pragma unroll
            for (int g = 0; g < 4; g++) g_bias[j * 4 + g] = bias[g][j];
        }
    }
    if (idx == 0) g_bar_count = 0;   // barrier reset per launch/replay
}

// ------------------------------- xproj GEMM (f32x2) ----------------------------
// xp[r][m] = sum_k x_row(r)[k] * Wx[k][m] + bias[m],  r = t*32 + b
// 128x128 tile, BK=8, 8x8 microtile, packed fp32 FMAs.
#define XBM 128
#define XBN 128
#define XBK 8

__global__ __launch_bounds__(256) void xproj_kernel(const float* __restrict__ x) {
    __shared__ float As[XBK][XBM + 4];
    __shared__ float Bs[XBK][XBN];

    int bn = blockIdx.x;               // 0..7    (m blocks)
    int bm = blockIdx.y;               // 0..511  (row blocks)
    int tid = threadIdx.x;
    int tx = tid & 15;                 // col group: m = m0 + tx*8 .. +8
    int ty = tid >> 4;                 // row group: r = r0 + ty*8 .. +8

    int r0 = bm * XBM;
    int m0 = bn * XBN;

    // A tile load mapping: arow = tid>>1 (0..127), akq = tid&1 (k-half)
    int arow = tid >> 1, akq = tid & 1;
    int r = r0 + arow;
    int b = r & 31, t = r >> 5;
    const float* arow_ptr = x + ((size_t)b * Ssz + t) * Isz;

    // B tile load mapping
    int bk = tid >> 5, bmq = tid & 31;
    const float* brow_ptr = g_Wx + (size_t)bk * Msz + m0 + bmq * 4;

    ull acc2[8][4];
    #pragma unroll
    for (int i = 0; i < 8; i++)
        #pragma unroll
        for (int jp = 0; jp < 4; jp++) acc2[i][jp] = 0ull;

    for (int k0 = 0; k0 < Isz; k0 += XBK) {
        float4 av = *(const float4*)(arow_ptr + k0 + akq * 4);
        As[akq * 4 + 0][arow] = av.x;
        As[akq * 4 + 1][arow] = av.y;
        As[akq * 4 + 2][arow] = av.z;
        As[akq * 4 + 3][arow] = av.w;
        *(float4*)&Bs[bk][bmq * 4] = *(const float4*)(brow_ptr + (size_t)k0 * Msz);
        __syncthreads();
        #pragma unroll
        for (int kk = 0; kk < XBK; kk++) {
            float4 aA = *(float4*)&As[kk][ty * 8];
            float4 aB = *(float4*)&As[kk][ty * 8 + 4];
            ulonglong2 bL = *(ulonglong2*)&Bs[kk][tx * 8];
            ulonglong2 bH = *(ulonglong2*)&Bs[kk][tx * 8 + 4];
            ull b2[4] = {bL.x, bL.y, bH.x, bH.y};
            float ar[8] = {aA.x, aA.y, aA.z, aA.w, aB.x, aB.y, aB.z, aB.w};
            #pragma unroll
            for (int i = 0; i < 8; i++) {
                ull a2 = pack2(ar[i], ar[i]);
                #pragma unroll
                for (int jp = 0; jp < 4; jp++) fma2(acc2[i][jp], a2, b2[jp]);
            }
        }
        __syncthreads();
    }

    ull bias2[4];
    {
        ulonglong2 bL = *(const ulonglong2*)(g_bias + m0 + tx * 8);
        ulonglong2 bH = *(const ulonglong2*)(g_bias + m0 + tx * 8 + 4);
        bias2[0] = bL.x; bias2[1] = bL.y; bias2[2] = bH.x; bias2[3] = bH.y;
    }
    #pragma unroll
    for (int i = 0; i < 8; i++) {
        int rr = r0 + ty * 8 + i;
        float* dst = g_xp + (size_t)rr * Msz + m0 + tx * 8;
        ulonglong2 oL, oH;
        oL.x = add2(acc2[i][0], bias2[0]);
        oL.y = add2(acc2[i][1], bias2[1]);
        oH.x = add2(acc2[i][2], bias2[2]);
        oH.y = add2(acc2[i][3], bias2[3]);
        *(ulonglong2*)dst = oL;
        *(ulonglong2*)(dst + 4) = oH;
    }
}

// ------------------------------- persistent recurrence -------------------------
// 128 CTAs x 256 threads. CTA = (jg in 0..31, bq in 0..3). Warp w: j = jg*8 + w,
// b-octet = bq. Lane l covers k in [8l, 8l+8). Wh duplicated-packed in registers.
// Inner GEMM uses f32x2 over batch pairs; 31-shuffle butterfly; monotonic
// release/acquire counting barrier with DRAM work hidden in the wait.
__global__ __launch_bounds__(256, 1) void lstm_rec(const float* __restrict__ h0,
                                                   const float* __restrict__ c0,
                                                   float* __restrict__ out,
                                                   int write_finals) {
    __shared__ float h_s[8 * Hsz];     // this CTA's 8 batch rows of h

    int cta = blockIdx.x;
    int jg = cta >> 2;
    int bq = cta & 3;
    int tid = threadIdx.x;
    int w = tid >> 5;
    int lane = tid & 31;
    int j = jg * 8 + w;

    // persistent duplicated weights: wd2[kk][g] = {Wh[lane*8+kk][4j+g]} x2
    ull wd2[8][4];
    #pragma unroll
    for (int kk = 0; kk < 8; kk++) {
        float4 v = *(const float4*)(g_Wh + (size_t)(lane * 8 + kk) * Msz + 4 * j);
        wd2[kk][0] = pack2(v.x, v.x);
        wd2[kk][1] = pack2(v.y, v.y);
        wd2[kk][2] = pack2(v.z, v.z);
        wd2[kk][3] = pack2(v.w, v.w);
    }

    int bb_me = lane >> 2;
    int g_me = lane & 3;
    int b_me = bq * 8 + bb_me;
    float c_val = c0[b_me * Hsz + j];   // meaningful on lanes with g_me==0

    unsigned* pcount = &g_bar_count;
    const size_t fin_off = (size_t)Bsz * Ssz * Hsz;

    float xv = g_xp[(size_t)b_me * Msz + 4 * j + g_me];   // t=0 prefetch

    for (int t = 0; t < Ssz; t++) {
        // cooperative load of h (prev step) into smem; bypass L1 (stale-line hazard)
        {
            const float4* src4 = (t == 0)
                ? (const float4*)(h0 + bq * 8 * Hsz)
                : (const float4*)(&g_hbuf[(t + 1) & 1][bq * 8 * Hsz]);
            float4* dst4 = (float4*)h_s;
            dst4[tid]       = __ldcg(src4 + tid);
            dst4[tid + 256] = __ldcg(src4 + tid + 256);
        }
        __syncthreads();

        ull acc2[4][4];
        #pragma unroll
        for (int p = 0; p < 4; p++)
            #pragma unroll
            for (int g = 0; g < 4; g++) acc2[p][g] = 0ull;

        #pragma unroll
        for (int bbp = 0; bbp < 4; bbp++) {
            float4 h0A = *(float4*)&h_s[(2 * bbp) * Hsz + lane * 8];
            float4 h0B = *(float4*)&h_s[(2 * bbp) * Hsz + lane * 8 + 4];
            float4 h1A = *(float4*)&h_s[(2 * bbp + 1) * Hsz + lane * 8];
            float4 h1B = *(float4*)&h_s[(2 * bbp + 1) * Hsz + lane * 8 + 4];
            float he[8] = {h0A.x, h0A.y, h0A.z, h0A.w, h0B.x, h0B.y, h0B.z, h0B.w};
            float ho[8] = {h1A.x, h1A.y, h1A.z, h1A.w, h1B.x, h1B.y, h1B.z, h1B.w};
            #pragma unroll
            for (int kk = 0; kk < 8; kk++) {
                ull hh = pack2(he[kk], ho[kk]);
                #pragma unroll
                for (int g = 0; g < 4; g++) fma2(acc2[bbp][g], wd2[kk][g], hh);
            }
        }

        // unpack to 32 scalars, order acc[bb*4+g]
        float acc[32];
        #pragma unroll
        for (int bbp = 0; bbp < 4; bbp++)
            #pragma unroll
            for (int g = 0; g < 4; g++)
                unpack2(acc[(2 * bbp) * 4 + g], acc[(2 * bbp + 1) * 4 + g], acc2[bbp][g]);

        // recursive-halving butterfly: lane L ends with full sum of value index L
        int cnt = 32;
        #pragma unroll
        for (int off = 16; off >= 1; off >>= 1) {
            cnt >>= 1;
            bool upper = (lane & off) != 0;
            #pragma unroll
            for (int v = 0; v < cnt; v++) {
                float send = upper ? acc[v] : acc[v + cnt];
                float recv = __shfl_xor_sync(0xffffffffu, send, off);
                acc[v] = (upper ? acc[v + cnt] : acc[v]) + recv;
            }
        }

        float pre = acc[0] + xv;   // bias already folded into xp
        float a;
        if (g_me == 2) {           // tanh(pre) = 2*sigmoid(2*pre) - 1
            float e = __expf(-2.f * pre);
            a = __fdividef(2.f, 1.f + e) - 1.f;
        } else {                   // sigmoid
            a = __fdividef(1.f, 1.f + __expf(-pre));
        }

        int base = lane & ~3;
        float fg = __shfl_sync(0xffffffffu, a, base);
        float ig = __shfl_sync(0xffffffffu, a, base + 1);
        float cg = __shfl_sync(0xffffffffu, a, base + 2);
        float og = __shfl_sync(0xffffffffu, a, base + 3);

        float hn = 0.f;
        if (g_me == 0) {
            c_val = c_val * fg + ig * cg;
            float e = __expf(-2.f * c_val);
            float th = __fdividef(2.f, 1.f + e) - 1.f;
            hn = og * th;
            g_hbuf[t & 1][b_me * Hsz + j] = hn;
        }

        __syncthreads();           // all h_hbuf stores + all h_s reads done

        int not_last = (t + 1 < Ssz);
        if (not_last && tid == 0) {
            // arrive: release orders the hbuf stores (via the barrier above)
            asm volatile("red.release.gpu.global.add.u32 [%0], %1;"
                         :: "l"(pcount), "r"(1u) : "memory");
        }

        // DRAM work hidden in the barrier wait:
        if (g_me == 0) {
            out[((size_t)b_me * Ssz + t) * Hsz + j] = hn;
            if (!not_last && write_finals) {
                out[fin_off + (size_t)b_me * Hsz + j] = hn;                           // h_f
                out[fin_off + (size_t)Bsz * Hsz + (size_t)b_me * Hsz + j] = c_val;    // c_f
            }
        }
        float xv_next = 0.f;
        if (not_last)
            xv_next = __ldg(g_xp + ((size_t)(t + 1) * Bsz + b_me) * Msz + 4 * j + g_me);

        if (not_last) {
            if (tid == 0) {
                unsigned target = (unsigned)NCTA_REC * (unsigned)(t + 1);
                unsigned vcur;
                do {
                    asm volatile("ld.acquire.gpu.global.u32 %0, [%1];"
                                 : "=r"(vcur) : "l"(pcount) : "memory");
                } while (vcur < target);
            }
            __syncthreads();
        }
        xv = xv_next;
    }
}

// ------------------------------- launch ----------------------------------------
extern "C" void kernel_launch(void* const* d_in, const int* in_sizes, int n_in,
                              void* d_out, int out_size) {
    const float* x  = (const float*)d_in[0];
    const float* h0 = (const float*)d_in[1];
    const float* c0 = (const float*)d_in[2];
    const float* Wf = (const float*)d_in[3];
    const float* bf = (const float*)d_in[4];
    const float* Wi = (const float*)d_in[5];
    const float* bi = (const float*)d_in[6];
    const float* Wc = (const float*)d_in[7];
    const float* bc = (const float*)d_in[8];
    const float* Wo = (const float*)d_in[9];
    const float* bo = (const float*)d_in[10];
    float* out = (float*)d_out;

    int full = Bsz * Ssz * Hsz + 2 * Bsz * Hsz;
    int write_finals = (out_size >= full) ? 1 : 0;

    pack_kernel<<<512, 256>>>(Wf, Wi, Wc, Wo, bf, bi, bc, bo);

    dim3 grid_x(8, 512);
    xproj_kernel<<<grid_x, 256>>>(x);

    lstm_rec<<<NCTA_REC, 256>>>(h0, c0, out, write_finals);
}